// round 16
// baseline (speedup 1.0000x reference)
#include <cuda_runtime.h>
#include <cuda_bf16.h>
#include <math.h>
#include <stdint.h>

#define HW 4096         // 64*64 spatial positions at feature res
#define CF 256          // feature channels
#define CO 64           // value channels (unalign_fb)
#define ALPHA 100.0f
#define XQ 4224         // padded (sorted) q length: 4096 + 8*16
#define XCH 264         // XQ/16 chunks
#define NQT 33          // GEMM1 q-tiles (128 wide)
#define NTILES (NQT * 32)
#define NPERS 296       // persistent CTAs (2 per SM x 148)
#define NV2 80          // GEMM2 cols: 64 ufb + 1 ones + 15 pad (5 n16 tiles)

// ---------------- device scratch (allocation-free) ----------------
__device__ uint32_t g_Xhi[(size_t)HW * XQ / 2]; // bf16x2 X plane (permuted q order)
__device__ __nv_bfloat16 g_faHi[HW * CF];
__device__ __nv_bfloat16 g_faLo[HW * CF];
__device__ __nv_bfloat16 g_fbHi[HW * CF];
__device__ __nv_bfloat16 g_fbLo[HW * CF];
__device__ __nv_bfloat16 g_Vthi[NV2 * XQ];   // V^T [col][pos]
__device__ __nv_bfloat16 g_Vtlo[NV2 * XQ];
__device__ float g_Wpart[32 * HW * NV2];     // (plane*4+slot) partials
__device__ float g_ufb[HW * CO];             // downsampled values, [q][c]
__device__ float g_meanA[CF];
__device__ float g_meanB[CF];
__device__ unsigned char g_maskA[3 * HW];
__device__ unsigned char g_codeB[HW];        // 3-bit code of mask_b per q
__device__ int g_perm[XQ];                   // pos -> original q (-1 = dummy)
__device__ unsigned char g_chunkSeg[XCH];    // seg(code) per 16-q chunk (0 = dead)
__device__ unsigned char g_tileSkip[NQT];    // 1 = entire 128-q tile dead
__device__ unsigned char g_slotSeg[32];      // seg per Wpart slot (0 = unused/ignored)
__device__ float g_U0[CO];                   // sum_q ufb[q][c]
__device__ float g_Bk[3 * CO];               // B_k[c] = sum_{q in mb_k} ufb[q][c]
__device__ float g_nbk[3];                   // |mb_k|
__device__ float g_aligned[HW * CO];         // [p][c]

// ---------------- helpers ----------------
__device__ __forceinline__ uint32_t smem_u32(const void* p) {
    uint32_t a;
    asm("{ .reg .u64 t; cvta.to.shared.u64 t, %1; cvt.u32.u64 %0, t; }" : "=r"(a) : "l"(p));
    return a;
}

#define LDSM_X4(r0, r1, r2, r3, addr) \
    asm volatile("ldmatrix.sync.aligned.m8n8.x4.shared.b16 {%0,%1,%2,%3}, [%4];" \
        : "=r"(r0), "=r"(r1), "=r"(r2), "=r"(r3) : "r"(addr))

__device__ __forceinline__ void mma_bf16(float* c, const uint32_t* a, uint32_t b0, uint32_t b1) {
    asm volatile(
        "mma.sync.aligned.m16n8k16.row.col.f32.bf16.bf16.f32 "
        "{%0,%1,%2,%3}, {%4,%5,%6,%7}, {%8,%9}, {%0,%1,%2,%3};"
        : "+f"(c[0]), "+f"(c[1]), "+f"(c[2]), "+f"(c[3])
        : "r"(a[0]), "r"(a[1]), "r"(a[2]), "r"(a[3]), "r"(b0), "r"(b1));
}

__device__ __forceinline__ void cp16(uint32_t saddr, const void* g) {
    asm volatile("cp.async.cg.shared.global [%0], [%1], 16;" :: "r"(saddr), "l"(g));
}
#define CP_COMMIT asm volatile("cp.async.commit_group;" ::: "memory")
#define CP_WAIT0  asm volatile("cp.async.wait_group 0;" ::: "memory")
#define CP_WAIT1  asm volatile("cp.async.wait_group 1;" ::: "memory")
#define CP_WAIT2  asm volatile("cp.async.wait_group 2;" ::: "memory")

// ---------------- 1) masks + deterministic stable code-sort (code 0 last) ----------------
__global__ void __launch_bounds__(512) k_maskperm(const int* __restrict__ fap,
                                                  const int* __restrict__ fbp) {
    __shared__ int s_cnt[8][513];
    __shared__ int s_start[8];
    __shared__ int s_end[8];
    int t = threadIdx.x;
    for (int i = t; i < XQ; i += 512) g_perm[i] = -1;
    if (t < 32) g_slotSeg[t] = 0;

    int codes[8];
#pragma unroll
    for (int j = 0; j < 8; j++) {
        int q = t * 8 + j;
        int y = (q >> 6) << 2, x = (q & 63) << 2;
        int off = y * 256 + x;
        unsigned code = 0;
#pragma unroll
        for (int k = 0; k < 3; k++) {
            g_maskA[k * HW + q] = (fap[(k + 1) * 65536 + off] != 0) ? 1 : 0;
            if (fbp[(k + 1) * 65536 + off] != 0) code |= (1u << k);
        }
        g_codeB[q] = (unsigned char)code;
        codes[j] = (int)code;
    }
    int c8[8] = {0, 0, 0, 0, 0, 0, 0, 0};
#pragma unroll
    for (int j = 0; j < 8; j++) c8[codes[j]]++;
#pragma unroll
    for (int c = 0; c < 8; c++) s_cnt[c][t + 1] = c8[c];
    if (t == 0)
#pragma unroll
        for (int c = 0; c < 8; c++) s_cnt[c][0] = 0;
    __syncthreads();
    for (int s = 1; s < 512; s <<= 1) {
        int v[8];
#pragma unroll
        for (int c = 0; c < 8; c++) v[c] = (t + 1 > s) ? s_cnt[c][t + 1 - s] : 0;
        __syncthreads();
#pragma unroll
        for (int c = 0; c < 8; c++) s_cnt[c][t + 1] += v[c];
        __syncthreads();
    }
    if (t == 0) {
        int st = 0;
        for (int i = 0; i < 8; i++) {
            int c = (i + 1) & 7;              // 1,2,...,7,0
            s_start[c] = st;
            st += (s_cnt[c][512] + 15) & ~15;
            s_end[c] = st;
        }
    }
    __syncthreads();
    int run[8];
#pragma unroll
    for (int c = 0; c < 8; c++) run[c] = s_start[c] + s_cnt[c][t];
#pragma unroll
    for (int j = 0; j < 8; j++) {
        int c = codes[j];
        g_perm[run[c]] = t * 8 + j;
        run[c]++;
    }
    __syncthreads();
    if (t < XCH) {
        int pos = t * 16, sg = 0;
        for (int c = 1; c < 8; c++)
            if (pos >= s_start[c] && pos < s_end[c]) sg = c;
        g_chunkSeg[t] = (unsigned char)sg;
    }
    __syncthreads();
    if (t < NQT) {
        int skip = 1;
        for (int j = 0; j < 8; j++)
            if (g_chunkSeg[t * 8 + j] != 0) skip = 0;
        g_tileSkip[t] = (unsigned char)skip;
    }
}

// ---------------- 2) per-channel spatial means ----------------
__global__ void k_mean(const float* __restrict__ fa, const float* __restrict__ fb) {
    int cb = blockIdx.x;
    int ch = cb & 255;
    const float* src = (cb < 256) ? fa : fb;
    float s = 0.f;
    for (int i = threadIdx.x; i < HW; i += 256) s += src[ch * HW + i];
    __shared__ float red[256];
    red[threadIdx.x] = s;
    __syncthreads();
    for (int st = 128; st > 0; st >>= 1) {
        if (threadIdx.x < st) red[threadIdx.x] += red[threadIdx.x + st];
        __syncthreads();
    }
    if (threadIdx.x == 0) {
        float m = red[0] / (float)HW;
        if (cb < 256) g_meanA[ch] = m; else g_meanB[ch] = m;
    }
}

// ---------------- 3) center + normalize + split, smem-transposed ----------------
__global__ void __launch_bounds__(256) k_norm(const float* __restrict__ fa,
                                              const float* __restrict__ fb) {
    __shared__ float sm[256 * 33];
    int t = threadIdx.x;
    int pb = blockIdx.x * 32;
    const float* src;  const float* mean;
    __nv_bfloat16 *dHi, *dLo;
    if (blockIdx.y == 0) { src = fa; mean = g_meanA; dHi = g_faHi; dLo = g_faLo; }
    else                 { src = fb; mean = g_meanB; dHi = g_fbHi; dLo = g_fbLo; }

#pragma unroll
    for (int i = 0; i < 32; i++) {
        int v = t + i * 256;
        int c = v >> 5, p = v & 31;
        sm[c * 33 + p] = src[c * HW + pb + p] - mean[c];
    }
    __syncthreads();

    int p = t >> 3, part = t & 7;
    float nsq = 0.f;
#pragma unroll
    for (int j = 0; j < 32; j++) {
        int c = part * 32 + ((j + part * 4) & 31);
        float v = sm[c * 33 + p];
        nsq += v * v;
    }
    nsq += __shfl_xor_sync(0xFFFFFFFF, nsq, 1);
    nsq += __shfl_xor_sync(0xFFFFFFFF, nsq, 2);
    nsq += __shfl_xor_sync(0xFFFFFFFF, nsq, 4);
    float inv = rsqrtf(nsq);

    size_t base = ((size_t)(pb + p) * CF + part * 32);
    uint32_t* hdst = (uint32_t*)(dHi + base);
    uint32_t* ldst = (uint32_t*)(dLo + base);
#pragma unroll
    for (int j = 0; j < 16; j++) {
        int c = part * 32 + j * 2;
        float v0 = sm[(c + 0) * 33 + p] * inv;
        float v1 = sm[(c + 1) * 33 + p] * inv;
        __nv_bfloat16 h0 = __float2bfloat16(v0), h1 = __float2bfloat16(v1);
        __nv_bfloat162 hp; hp.x = h0; hp.y = h1;
        __nv_bfloat16 l0 = __float2bfloat16(v0 - __bfloat162float(h0));
        __nv_bfloat16 l1 = __float2bfloat16(v1 - __bfloat162float(h1));
        __nv_bfloat162 lp; lp.x = l0; lp.y = l1;
        hdst[j] = *(uint32_t*)&hp;
        ldst[j] = *(uint32_t*)&lp;
    }
}

// ---------------- 4) bilinear downsample 256->64 ----------------
__global__ void k_ufb(const float* __restrict__ ub) {
    int idx = blockIdx.x * 256 + threadIdx.x;
    if (idx >= HW * CO) return;
    int c = idx & 63, q = idx >> 6;
    int i = q >> 6, j = q & 63;
    const float sc = 255.0f / 63.0f;
    float ry = (float)i * sc, rx = (float)j * sc;
    int y0 = (int)ry, x0 = (int)rx;
    int y1 = min(y0 + 1, 255), x1 = min(x0 + 1, 255);
    float wy = ry - (float)y0, wx = rx - (float)x0;
    const float* b = ub + c * 65536;
    float v00 = b[y0 * 256 + x0], v01 = b[y0 * 256 + x1];
    float v10 = b[y1 * 256 + x0], v11 = b[y1 * 256 + x1];
    float r0 = v00 * (1.f - wy) + v10 * wy;
    float r1 = v01 * (1.f - wy) + v11 * wy;
    g_ufb[q * CO + c] = r0 * (1.f - wx) + r1 * wx;
}

// ---------------- 5) U0[c], Bk[k][c], nbk ----------------
__global__ void k_ub() {
    int c = blockIdx.x;
    __shared__ float s_acc[4];
    __shared__ int   s_n[3];
    if (threadIdx.x < 4) s_acc[threadIdx.x] = 0.f;
    if (threadIdx.x < 3) s_n[threadIdx.x] = 0;
    __syncthreads();
    float a0 = 0, b0 = 0, b1 = 0, b2 = 0;
    int n0 = 0, n1 = 0, n2 = 0;
    for (int q = threadIdx.x; q < HW; q += 256) {
        float u = g_ufb[q * CO + c];
        int code = g_codeB[q];
        a0 += u;
        if (code & 1) { b0 += u; n0++; }
        if (code & 2) { b1 += u; n1++; }
        if (code & 4) { b2 += u; n2++; }
    }
    atomicAdd(&s_acc[0], a0);
    atomicAdd(&s_acc[1], b0);
    atomicAdd(&s_acc[2], b1);
    atomicAdd(&s_acc[3], b2);
    if (c == 0) {
        atomicAdd(&s_n[0], n0); atomicAdd(&s_n[1], n1); atomicAdd(&s_n[2], n2);
    }
    __syncthreads();
    if (threadIdx.x == 0) g_U0[c] = s_acc[0];
    if (threadIdx.x < 3) {
        g_Bk[threadIdx.x * CO + c] = s_acc[1 + threadIdx.x];
        if (c == 0) g_nbk[threadIdx.x] = (float)s_n[threadIdx.x];
    }
}

// ---------------- 5b) build V^T planes (permuted rows) ----------------
__global__ void k_V() {
    int idx = blockIdx.x * 256 + threadIdx.x;   // col*XQ + pos
    if (idx >= NV2 * XQ) return;
    int col = idx / XQ, pos = idx % XQ;
    int q = g_perm[pos];
    float v = 0.f;
    if (q >= 0) {
        if (col < 64) v = g_ufb[q * CO + col];
        else if (col == 64) v = 1.0f;
    }
    __nv_bfloat16 h = __float2bfloat16(v);
    g_Vthi[idx] = h;
    g_Vtlo[idx] = __float2bfloat16(v - __bfloat162float(h));
}

// ---------------- 6) GEMM1: persistent CTAs, split-bf16, 128x128, 2-stage k32 ----------------
#define G1_PLANE 10240              // 128 rows * 80 bytes
#define G1_SMEM  (2 * 4 * G1_PLANE) // 81920

__device__ __forceinline__ void g1_prefetch(uint32_t sb, int buf, int kc,
                                            int pb, int qb, int t) {
    int kof = kc * 32;
#pragma unroll
    for (int i = 0; i < 8; i++) {
        int v = t + i * 256;
        int plane = v >> 9, r = (v >> 2) & 127, seg = v & 3;
        uint32_t sa = sb + (uint32_t)(buf * (4 * G1_PLANE) + plane * G1_PLANE + r * 80 + seg * 16);
        const __nv_bfloat16* src = (plane == 0) ? g_faHi : (plane == 1) ? g_faLo
                                 : (plane == 2) ? g_fbHi : g_fbLo;
        int row;
        if (plane < 2) row = pb + r;
        else { row = __ldg(&g_perm[qb + r]); if (row < 0) row = 0; }
        cp16(sa, (const char*)src + ((size_t)row * CF + kof + seg * 8) * 2);
    }
}

__global__ void __launch_bounds__(256, 2) k_gemm_mma() {
    extern __shared__ char smem[];
    uint32_t sb = smem_u32(smem);
    int t = threadIdx.x, w = t >> 5, l = t & 31;
    int wm = w >> 1, wn = w & 1;

    int rowA = wm * 32 + (l & 15);
    int rowB = wn * 64 + (l & 15);
    uint32_t colb = (uint32_t)((l >> 4) << 4);

    for (int tile = blockIdx.x; tile < NTILES; tile += NPERS) {
        int qt = tile % NQT;
        if (g_tileSkip[qt]) continue;
        int qb = qt << 7, pb = (tile / NQT) << 7;

        float acc[2][8][4] = {};

        g1_prefetch(sb, 0, 0, pb, qb, t); CP_COMMIT;

        for (int kc = 0; kc < 8; kc++) {
            if (kc < 7) { g1_prefetch(sb, (kc + 1) & 1, kc + 1, pb, qb, t); CP_COMMIT; CP_WAIT1; }
            else CP_WAIT0;
            __syncthreads();

            uint32_t baseA = sb + (uint32_t)((kc & 1) * (4 * G1_PLANE));
            uint32_t baseB = baseA + 2 * G1_PLANE;

#pragma unroll
            for (int kk2 = 0; kk2 < 2; kk2++) {
                uint32_t kb = (uint32_t)(kk2 * 32) + colb;
                uint32_t ah[2][4], al[2][4];
#pragma unroll
                for (int mi = 0; mi < 2; mi++) {
                    uint32_t ad = baseA + (uint32_t)((rowA + mi * 16) * 80) + kb;
                    LDSM_X4(ah[mi][0], ah[mi][1], ah[mi][2], ah[mi][3], ad);
                    LDSM_X4(al[mi][0], al[mi][1], al[mi][2], al[mi][3], ad + G1_PLANE);
                }
#pragma unroll
                for (int np = 0; np < 4; np++) {
                    uint32_t bd = baseB + (uint32_t)((rowB + np * 16) * 80) + kb;
                    uint32_t bh[4], bl[4];
                    LDSM_X4(bh[0], bh[1], bh[2], bh[3], bd);
                    LDSM_X4(bl[0], bl[1], bl[2], bl[3], bd + G1_PLANE);
                    mma_bf16(acc[0][np * 2 + 0], ah[0], bh[0], bh[2]);
                    mma_bf16(acc[0][np * 2 + 1], ah[0], bh[1], bh[3]);
                    mma_bf16(acc[1][np * 2 + 0], ah[1], bh[0], bh[2]);
                    mma_bf16(acc[1][np * 2 + 1], ah[1], bh[1], bh[3]);
                    mma_bf16(acc[0][np * 2 + 0], ah[0], bl[0], bl[2]);
                    mma_bf16(acc[0][np * 2 + 1], ah[0], bl[1], bl[3]);
                    mma_bf16(acc[1][np * 2 + 0], ah[1], bl[0], bl[2]);
                    mma_bf16(acc[1][np * 2 + 1], ah[1], bl[1], bl[3]);
                    mma_bf16(acc[0][np * 2 + 0], al[0], bh[0], bh[2]);
                    mma_bf16(acc[0][np * 2 + 1], al[0], bh[1], bh[3]);
                    mma_bf16(acc[1][np * 2 + 0], al[1], bh[0], bh[2]);
                    mma_bf16(acc[1][np * 2 + 1], al[1], bh[1], bh[3]);
                }
            }
            __syncthreads();
        }

        // ---- epilogue: exp + bf16 X store (hi plane only) ----
        int prl = wm * 32 + (l >> 2);
        int qcl = wn * 64 + (l & 3) * 2;
#pragma unroll
        for (int mi = 0; mi < 2; mi++) {
#pragma unroll
            for (int nj = 0; nj < 8; nj++) {
#pragma unroll
                for (int half = 0; half < 2; half++) {
                    int rloc = prl + mi * 16 + half * 8;
                    int qloc = qcl + nj * 8;
                    float x0 = __expf(fminf(ALPHA * acc[mi][nj][half * 2 + 0], 80.f));
                    float x1 = __expf(fminf(ALPHA * acc[mi][nj][half * 2 + 1], 80.f));
                    __nv_bfloat16 h0 = __float2bfloat16(x0);
                    __nv_bfloat16 h1 = __float2bfloat16(x1);
                    __nv_bfloat162 hp; hp.x = h0; hp.y = h1;
                    size_t idx = ((size_t)(pb + rloc) * XQ + qb + qloc) >> 1;
                    g_Xhi[idx] = *(uint32_t*)&hp;
                }
            }
        }
        __syncthreads();
    }
}

// ---------------- 7) GEMM2: 128-row CTAs, hi-only X, 2 combos, dead-chunk skip ----------------
#define W2RS 48
#define W2A (128 * W2RS)                // 6144 (single X plane)
#define W2B (NV2 * W2RS)                // 3840
#define W2ST (W2A + 2 * W2B)            // 13824
#define W2SMEM (4 * W2ST)               // 55296
#define W2SLOTS (256 + 320)             // A: 128x2, B: 80x2x2

__device__ __forceinline__ void g2_prefetch(uint32_t sb, int s, int qof, int pb, int t) {
#pragma unroll
    for (int i = 0; i < 3; i++) {
        int v = t + i * 256;
        if (v >= W2SLOTS) break;
        if (v < 256) {
            int r = v >> 1, seg = v & 1;
            uint32_t sa = sb + (uint32_t)(s * W2ST + r * W2RS + seg * 16);
            cp16(sa, (const char*)g_Xhi + ((size_t)(pb + r) * XQ + qof) * 2 + seg * 16);
        } else {
            int v2 = v - 256;
            int plane = (v2 >= NV2 * 2) ? 1 : 0;
            int r = (v2 - plane * NV2 * 2) >> 1, seg = v2 & 1;
            uint32_t sa = sb + (uint32_t)(s * W2ST + W2A + plane * W2B + r * W2RS + seg * 16);
            const __nv_bfloat16* vp = plane ? g_Vtlo : g_Vthi;
            cp16(sa, (const char*)vp + ((size_t)r * XQ + qof + seg * 8) * 2);
        }
    }
}

__device__ __forceinline__ void g2_flush(float acc[2][6][4], int nt, int pb, int wm, int wn,
                                         int l, int plane, int slot, int seg) {
    float* Wp = g_Wpart + (size_t)(plane * 4 + slot) * HW * NV2;
    int cb2 = (l & 3) * 2;
#pragma unroll
    for (int mi = 0; mi < 2; mi++) {
        int r0 = pb + wm * 32 + mi * 16 + (threadIdx.x % 32 >> 2);
#pragma unroll
        for (int np = 0; np < 3; np++) {
            if (np < nt) {
#pragma unroll
                for (int n8 = 0; n8 < 2; n8++) {
                    int col = wn * 48 + np * 16 + n8 * 8 + cb2;
                    float* a = acc[mi][np * 2 + n8];
                    *(float2*)&Wp[(size_t)r0 * NV2 + col]       = make_float2(a[0], a[1]);
                    *(float2*)&Wp[(size_t)(r0 + 8) * NV2 + col] = make_float2(a[2], a[3]);
                    a[0] = a[1] = a[2] = a[3] = 0.f;
                }
            }
        }
    }
    if (threadIdx.x == 0) g_slotSeg[plane * 4 + slot] = (unsigned char)seg;
    (void)l;
}

__global__ void __launch_bounds__(256, 2) k_gemm2() {
    extern __shared__ char smem[];
    uint32_t sb = smem_u32(smem);
    int t = threadIdx.x, w = t >> 5, l = t & 31;
    int pb = blockIdx.x << 7;         // 128 rows per CTA, grid.x = 32
    int plane = blockIdx.y;           // 0..7
    int cbase = plane * 33;
    int q0 = plane * 528;
    int wm = w & 3, wn = w >> 2;
    int nt = wn ? 2 : 3;

    float acc[2][6][4] = {};
    int curSeg = g_chunkSeg[cbase];
    int slot = 0;

    uint32_t colb = (uint32_t)((l >> 4) << 4);

    g2_prefetch(sb, 0, q0, pb, t); CP_COMMIT;
    g2_prefetch(sb, 1, q0 + 16, pb, t); CP_COMMIT;
    g2_prefetch(sb, 2, q0 + 32, pb, t); CP_COMMIT;

    for (int kc = 0; kc < 33; kc++) {
        CP_WAIT2;
        __syncthreads();
        if (kc <= 29) g2_prefetch(sb, (kc + 3) & 3, q0 + (kc + 3) * 16, pb, t);
        CP_COMMIT;

        int sg = g_chunkSeg[cbase + kc];
        if (sg != curSeg) {
            if (curSeg) {
                g2_flush(acc, nt, pb, wm, wn, l, plane, slot, curSeg);
                slot = min(slot + 1, 3);
            }
            curSeg = sg;
        }
        if (!sg) continue;            // dead chunk (code 0 / pad)

        uint32_t baseA = sb + (uint32_t)((kc & 3) * W2ST);
        uint32_t baseB = baseA + W2A;

        uint32_t ah[2][4];
#pragma unroll
        for (int mi = 0; mi < 2; mi++) {
            uint32_t ad = baseA + (uint32_t)((wm * 32 + mi * 16 + (l & 15)) * W2RS) + colb;
            LDSM_X4(ah[mi][0], ah[mi][1], ah[mi][2], ah[mi][3], ad);
        }
#pragma unroll
        for (int np = 0; np < 3; np++) {
            if (np < nt) {
                uint32_t bd = baseB + (uint32_t)((wn * 48 + np * 16 + (l & 15)) * W2RS) + colb;
                uint32_t bh[4], bl[4];
                LDSM_X4(bh[0], bh[1], bh[2], bh[3], bd);
                LDSM_X4(bl[0], bl[1], bl[2], bl[3], bd + W2B);
                mma_bf16(acc[0][np * 2 + 0], ah[0], bh[0], bh[2]);
                mma_bf16(acc[0][np * 2 + 1], ah[0], bh[1], bh[3]);
                mma_bf16(acc[1][np * 2 + 0], ah[1], bh[0], bh[2]);
                mma_bf16(acc[1][np * 2 + 1], ah[1], bh[1], bh[3]);
                mma_bf16(acc[0][np * 2 + 0], ah[0], bl[0], bl[2]);
                mma_bf16(acc[0][np * 2 + 1], ah[0], bl[1], bl[3]);
                mma_bf16(acc[1][np * 2 + 0], ah[1], bl[0], bl[2]);
                mma_bf16(acc[1][np * 2 + 1], ah[1], bl[1], bl[3]);
            }
        }
    }
    if (curSeg) g2_flush(acc, nt, pb, wm, wn, l, plane, slot, curSeg);
}

// ---------------- 8) combine: sum slots by code-bit membership ----------------
__global__ void k_combine() {
    int idx = blockIdx.x * 256 + threadIdx.x;   // p*64 + c
    if (idx >= HW * CO) return;
    int p = idx >> 6, c = idx & 63;
    float Wk[3] = {0.f, 0.f, 0.f}, Ek[3] = {0.f, 0.f, 0.f};
#pragma unroll
    for (int s = 0; s < 32; s++) {
        int sg = g_slotSeg[s];
        if (!sg) continue;
        const float* Wp = g_Wpart + (size_t)s * HW * NV2 + (size_t)p * NV2;
        float wv = Wp[c], ev = Wp[64];
        if (sg & 1) { Wk[0] += wv; Ek[0] += ev; }
        if (sg & 2) { Wk[1] += wv; Ek[1] += ev; }
        if (sg & 4) { Wk[2] += wv; Ek[2] += ev; }
    }
    float comb = 0.f, msum = 0.f;
#pragma unroll
    for (int k = 0; k < 3; k++) {
        if (g_maskA[k * HW + p]) {
            msum += 1.f;
            float denom = Ek[k] + (4096.0f - g_nbk[k]);
            comb += (Wk[k] + g_U0[c] - g_Bk[k * CO + c]) / denom;
        }
    }
    g_aligned[idx] = comb / fmaxf(msum, 1.0f);
}

// ---------------- 9) bilinear upsample 64 -> 256 ----------------
__global__ void __launch_bounds__(256) k_up(float* __restrict__ out) {
    __shared__ float sm[64 * 65];
    int t = threadIdx.x;
    int Y = blockIdx.x;
    const float sc = 63.0f / 255.0f;
    float ry = (float)Y * sc;
    int y0 = (int)ry;
    int y1 = min(y0 + 1, 63);
    float wy = ry - (float)y0;

    const float* A0 = g_aligned + (size_t)(y0 << 6) * CO;
    const float* A1 = g_aligned + (size_t)(y1 << 6) * CO;
#pragma unroll
    for (int i = 0; i < 16; i++) {
        int v = t + i * 256;
        int x = v >> 6, c = v & 63;
        float a = A0[v], b = A1[v];
        sm[c * 65 + x] = a + (b - a) * wy;
    }
    __syncthreads();

#pragma unroll
    for (int i = 0; i < 64; i++) {
        int v = t + i * 256;
        int c = v >> 8, X = v & 255;
        float rx = (float)X * sc;
        int x0 = (int)rx;
        int x1 = min(x0 + 1, 63);
        float wx = rx - (float)x0;
        float a = sm[c * 65 + x0], b = sm[c * 65 + x1];
        out[(size_t)c * 65536 + Y * 256 + X] = a + (b - a) * wx;
    }
}

// ---------------- launch ----------------
extern "C" void kernel_launch(void* const* d_in, const int* in_sizes, int n_in,
                              void* d_out, int out_size) {
    const float* ufb_in = (const float*)d_in[0];   // (1,64,256,256)
    const float* fa     = (const float*)d_in[1];   // (1,256,64,64)
    const int*   fap    = (const int*)  d_in[2];   // (1,4,256,256)
    const float* fb     = (const float*)d_in[3];   // (1,256,64,64)
    const int*   fbp    = (const int*)  d_in[4];   // (1,4,256,256)
    float* out = (float*)d_out;                    // (1,64,256,256)

    static cudaStream_t s1 = nullptr;
    static cudaEvent_t e0 = nullptr, ePerm = nullptr, eV = nullptr;
    if (!s1) {
        cudaStreamCreateWithFlags(&s1, cudaStreamNonBlocking);
        cudaEventCreateWithFlags(&e0, cudaEventDisableTiming);
        cudaEventCreateWithFlags(&ePerm, cudaEventDisableTiming);
        cudaEventCreateWithFlags(&eV, cudaEventDisableTiming);
        cudaFuncSetAttribute(k_gemm_mma, cudaFuncAttributeMaxDynamicSharedMemorySize, G1_SMEM);
        cudaFuncSetAttribute(k_gemm2,    cudaFuncAttributeMaxDynamicSharedMemorySize, W2SMEM);
    }

    // fork
    cudaEventRecord(e0, 0);
    cudaStreamWaitEvent(s1, e0, 0);

    k_maskperm<<<1, 512, 0, s1>>>(fap, fbp);               // 1 (s1): masks + sort
    cudaEventRecord(ePerm, s1);
    k_mean<<<512, 256>>>(fa, fb);                          // 2 (s0)
    k_norm<<<dim3(128, 2), 256>>>(fa, fb);                 // 3 (s0)
    cudaStreamWaitEvent(0, ePerm, 0);
    k_gemm_mma<<<NPERS, 256, G1_SMEM>>>();                 // 4 (s0) -> profiled, persistent
    k_ufb<<<(HW * CO) / 256, 256, 0, s1>>>(ufb_in);        // 5 (s1, overlaps GEMM1)
    k_ub<<<64, 256, 0, s1>>>();                            // 6 (s1)
    k_V<<<(NV2 * XQ + 255) / 256, 256, 0, s1>>>();         // 7 (s1)
    cudaEventRecord(eV, s1);
    cudaStreamWaitEvent(0, eV, 0);

    k_gemm2<<<dim3(32, 8), 256, W2SMEM>>>();
    k_combine<<<(HW * CO) / 256, 256>>>();
    k_up<<<256, 256>>>(out);
}

// round 17
// speedup vs baseline: 1.1056x; 1.1056x over previous
#include <cuda_runtime.h>
#include <cuda_bf16.h>
#include <math.h>
#include <stdint.h>

#define HW 4096         // 64*64 spatial positions at feature res
#define CF 256          // feature channels
#define CO 64           // value channels (unalign_fb)
#define ALPHA 100.0f
#define XQ 4224         // padded (sorted) q length: 4096 + 8*16
#define XCH 264         // XQ/16 chunks
#define NQT 33          // GEMM1 q-tiles (128 wide)
#define NV2 80          // GEMM2 cols: 64 ufb + 1 ones + 15 pad (5 n16 tiles)

// ---------------- device scratch (allocation-free) ----------------
__device__ uint32_t g_Xhi[(size_t)HW * XQ / 2]; // bf16x2 X plane (permuted q order)
__device__ __nv_bfloat16 g_faHi[HW * CF];
__device__ __nv_bfloat16 g_faLo[HW * CF];
__device__ __nv_bfloat16 g_fbHi[HW * CF];
__device__ __nv_bfloat16 g_fbLo[HW * CF];
__device__ __nv_bfloat16 g_Vthi[NV2 * XQ];   // V^T [col][pos]
__device__ __nv_bfloat16 g_Vtlo[NV2 * XQ];
__device__ float g_Wpart[32 * HW * NV2];     // (plane*4+slot) partials
__device__ float g_ufb[HW * CO];             // downsampled values, [q][c]
__device__ float g_meanA[CF];
__device__ float g_meanB[CF];
__device__ unsigned char g_maskA[3 * HW];
__device__ unsigned char g_codeB[HW];        // 3-bit code of mask_b per q
__device__ int g_perm[XQ];                   // pos -> original q (-1 = dummy)
__device__ unsigned char g_chunkSeg[XCH];    // seg(code) per 16-q chunk (0 = dead)
__device__ unsigned char g_tileSkip[NQT];    // 1 = entire 128-q tile dead
__device__ unsigned char g_slotSeg[32];      // seg per Wpart slot (0 = unused/ignored)
__device__ float g_U0[CO];                   // sum_q ufb[q][c]
__device__ float g_Bk[3 * CO];               // B_k[c] = sum_{q in mb_k} ufb[q][c]
__device__ float g_nbk[3];                   // |mb_k|
__device__ float g_aligned[HW * CO];         // [p][c]

// ---------------- helpers ----------------
__device__ __forceinline__ uint32_t smem_u32(const void* p) {
    uint32_t a;
    asm("{ .reg .u64 t; cvta.to.shared.u64 t, %1; cvt.u32.u64 %0, t; }" : "=r"(a) : "l"(p));
    return a;
}

#define LDSM_X4(r0, r1, r2, r3, addr) \
    asm volatile("ldmatrix.sync.aligned.m8n8.x4.shared.b16 {%0,%1,%2,%3}, [%4];" \
        : "=r"(r0), "=r"(r1), "=r"(r2), "=r"(r3) : "r"(addr))

__device__ __forceinline__ void mma_bf16(float* c, const uint32_t* a, uint32_t b0, uint32_t b1) {
    asm volatile(
        "mma.sync.aligned.m16n8k16.row.col.f32.bf16.bf16.f32 "
        "{%0,%1,%2,%3}, {%4,%5,%6,%7}, {%8,%9}, {%0,%1,%2,%3};"
        : "+f"(c[0]), "+f"(c[1]), "+f"(c[2]), "+f"(c[3])
        : "r"(a[0]), "r"(a[1]), "r"(a[2]), "r"(a[3]), "r"(b0), "r"(b1));
}

__device__ __forceinline__ void cp16(uint32_t saddr, const void* g) {
    asm volatile("cp.async.cg.shared.global [%0], [%1], 16;" :: "r"(saddr), "l"(g));
}
#define CP_COMMIT asm volatile("cp.async.commit_group;" ::: "memory")
#define CP_WAIT0  asm volatile("cp.async.wait_group 0;" ::: "memory")
#define CP_WAIT1  asm volatile("cp.async.wait_group 1;" ::: "memory")
#define CP_WAIT2  asm volatile("cp.async.wait_group 2;" ::: "memory")

// ---------------- 1) masks + deterministic stable code-sort (code 0 last) ----------------
__global__ void __launch_bounds__(512) k_maskperm(const int* __restrict__ fap,
                                                  const int* __restrict__ fbp) {
    __shared__ int s_cnt[8][513];
    __shared__ int s_start[8];
    __shared__ int s_end[8];
    int t = threadIdx.x;
    for (int i = t; i < XQ; i += 512) g_perm[i] = -1;
    if (t < 32) g_slotSeg[t] = 0;

    int codes[8];
#pragma unroll
    for (int j = 0; j < 8; j++) {
        int q = t * 8 + j;
        int y = (q >> 6) << 2, x = (q & 63) << 2;
        int off = y * 256 + x;
        unsigned code = 0;
#pragma unroll
        for (int k = 0; k < 3; k++) {
            g_maskA[k * HW + q] = (fap[(k + 1) * 65536 + off] != 0) ? 1 : 0;
            if (fbp[(k + 1) * 65536 + off] != 0) code |= (1u << k);
        }
        g_codeB[q] = (unsigned char)code;
        codes[j] = (int)code;
    }
    int c8[8] = {0, 0, 0, 0, 0, 0, 0, 0};
#pragma unroll
    for (int j = 0; j < 8; j++) c8[codes[j]]++;
#pragma unroll
    for (int c = 0; c < 8; c++) s_cnt[c][t + 1] = c8[c];
    if (t == 0)
#pragma unroll
        for (int c = 0; c < 8; c++) s_cnt[c][0] = 0;
    __syncthreads();
    for (int s = 1; s < 512; s <<= 1) {
        int v[8];
#pragma unroll
        for (int c = 0; c < 8; c++) v[c] = (t + 1 > s) ? s_cnt[c][t + 1 - s] : 0;
        __syncthreads();
#pragma unroll
        for (int c = 0; c < 8; c++) s_cnt[c][t + 1] += v[c];
        __syncthreads();
    }
    if (t == 0) {
        int st = 0;
        for (int i = 0; i < 8; i++) {
            int c = (i + 1) & 7;              // 1,2,...,7,0
            s_start[c] = st;
            st += (s_cnt[c][512] + 15) & ~15;
            s_end[c] = st;
        }
    }
    __syncthreads();
    int run[8];
#pragma unroll
    for (int c = 0; c < 8; c++) run[c] = s_start[c] + s_cnt[c][t];
#pragma unroll
    for (int j = 0; j < 8; j++) {
        int c = codes[j];
        g_perm[run[c]] = t * 8 + j;
        run[c]++;
    }
    __syncthreads();
    if (t < XCH) {
        int pos = t * 16, sg = 0;
        for (int c = 1; c < 8; c++)
            if (pos >= s_start[c] && pos < s_end[c]) sg = c;
        g_chunkSeg[t] = (unsigned char)sg;
    }
    __syncthreads();
    if (t < NQT) {
        int skip = 1;
        for (int j = 0; j < 8; j++)
            if (g_chunkSeg[t * 8 + j] != 0) skip = 0;
        g_tileSkip[t] = (unsigned char)skip;
    }
}

// ---------------- 2) per-channel spatial means ----------------
__global__ void k_mean(const float* __restrict__ fa, const float* __restrict__ fb) {
    int cb = blockIdx.x;
    int ch = cb & 255;
    const float* src = (cb < 256) ? fa : fb;
    float s = 0.f;
    for (int i = threadIdx.x; i < HW; i += 256) s += src[ch * HW + i];
    __shared__ float red[256];
    red[threadIdx.x] = s;
    __syncthreads();
    for (int st = 128; st > 0; st >>= 1) {
        if (threadIdx.x < st) red[threadIdx.x] += red[threadIdx.x + st];
        __syncthreads();
    }
    if (threadIdx.x == 0) {
        float m = red[0] / (float)HW;
        if (cb < 256) g_meanA[ch] = m; else g_meanB[ch] = m;
    }
}

// ---------------- 3) center + normalize + split, smem-transposed ----------------
__global__ void __launch_bounds__(256) k_norm(const float* __restrict__ fa,
                                              const float* __restrict__ fb) {
    __shared__ float sm[256 * 33];
    int t = threadIdx.x;
    int pb = blockIdx.x * 32;
    const float* src;  const float* mean;
    __nv_bfloat16 *dHi, *dLo;
    if (blockIdx.y == 0) { src = fa; mean = g_meanA; dHi = g_faHi; dLo = g_faLo; }
    else                 { src = fb; mean = g_meanB; dHi = g_fbHi; dLo = g_fbLo; }

#pragma unroll
    for (int i = 0; i < 32; i++) {
        int v = t + i * 256;
        int c = v >> 5, p = v & 31;
        sm[c * 33 + p] = src[c * HW + pb + p] - mean[c];
    }
    __syncthreads();

    int p = t >> 3, part = t & 7;
    float nsq = 0.f;
#pragma unroll
    for (int j = 0; j < 32; j++) {
        int c = part * 32 + ((j + part * 4) & 31);
        float v = sm[c * 33 + p];
        nsq += v * v;
    }
    nsq += __shfl_xor_sync(0xFFFFFFFF, nsq, 1);
    nsq += __shfl_xor_sync(0xFFFFFFFF, nsq, 2);
    nsq += __shfl_xor_sync(0xFFFFFFFF, nsq, 4);
    float inv = rsqrtf(nsq);

    size_t base = ((size_t)(pb + p) * CF + part * 32);
    uint32_t* hdst = (uint32_t*)(dHi + base);
    uint32_t* ldst = (uint32_t*)(dLo + base);
#pragma unroll
    for (int j = 0; j < 16; j++) {
        int c = part * 32 + j * 2;
        float v0 = sm[(c + 0) * 33 + p] * inv;
        float v1 = sm[(c + 1) * 33 + p] * inv;
        __nv_bfloat16 h0 = __float2bfloat16(v0), h1 = __float2bfloat16(v1);
        __nv_bfloat162 hp; hp.x = h0; hp.y = h1;
        __nv_bfloat16 l0 = __float2bfloat16(v0 - __bfloat162float(h0));
        __nv_bfloat16 l1 = __float2bfloat16(v1 - __bfloat162float(h1));
        __nv_bfloat162 lp; lp.x = l0; lp.y = l1;
        hdst[j] = *(uint32_t*)&hp;
        ldst[j] = *(uint32_t*)&lp;
    }
}

// ---------------- 4) bilinear downsample 256->64 ----------------
__global__ void k_ufb(const float* __restrict__ ub) {
    int idx = blockIdx.x * 256 + threadIdx.x;
    if (idx >= HW * CO) return;
    int c = idx & 63, q = idx >> 6;
    int i = q >> 6, j = q & 63;
    const float sc = 255.0f / 63.0f;
    float ry = (float)i * sc, rx = (float)j * sc;
    int y0 = (int)ry, x0 = (int)rx;
    int y1 = min(y0 + 1, 255), x1 = min(x0 + 1, 255);
    float wy = ry - (float)y0, wx = rx - (float)x0;
    const float* b = ub + c * 65536;
    float v00 = b[y0 * 256 + x0], v01 = b[y0 * 256 + x1];
    float v10 = b[y1 * 256 + x0], v11 = b[y1 * 256 + x1];
    float r0 = v00 * (1.f - wy) + v10 * wy;
    float r1 = v01 * (1.f - wy) + v11 * wy;
    g_ufb[q * CO + c] = r0 * (1.f - wx) + r1 * wx;
}

// ---------------- 5) U0[c], Bk[k][c], nbk ----------------
__global__ void k_ub() {
    int c = blockIdx.x;
    __shared__ float s_acc[4];
    __shared__ int   s_n[3];
    if (threadIdx.x < 4) s_acc[threadIdx.x] = 0.f;
    if (threadIdx.x < 3) s_n[threadIdx.x] = 0;
    __syncthreads();
    float a0 = 0, b0 = 0, b1 = 0, b2 = 0;
    int n0 = 0, n1 = 0, n2 = 0;
    for (int q = threadIdx.x; q < HW; q += 256) {
        float u = g_ufb[q * CO + c];
        int code = g_codeB[q];
        a0 += u;
        if (code & 1) { b0 += u; n0++; }
        if (code & 2) { b1 += u; n1++; }
        if (code & 4) { b2 += u; n2++; }
    }
    atomicAdd(&s_acc[0], a0);
    atomicAdd(&s_acc[1], b0);
    atomicAdd(&s_acc[2], b1);
    atomicAdd(&s_acc[3], b2);
    if (c == 0) {
        atomicAdd(&s_n[0], n0); atomicAdd(&s_n[1], n1); atomicAdd(&s_n[2], n2);
    }
    __syncthreads();
    if (threadIdx.x == 0) g_U0[c] = s_acc[0];
    if (threadIdx.x < 3) {
        g_Bk[threadIdx.x * CO + c] = s_acc[1 + threadIdx.x];
        if (c == 0) g_nbk[threadIdx.x] = (float)s_n[threadIdx.x];
    }
}

// ---------------- 5b) build V^T planes (permuted rows) ----------------
__global__ void k_V() {
    int idx = blockIdx.x * 256 + threadIdx.x;   // col*XQ + pos
    if (idx >= NV2 * XQ) return;
    int col = idx / XQ, pos = idx % XQ;
    int q = g_perm[pos];
    float v = 0.f;
    if (q >= 0) {
        if (col < 64) v = g_ufb[q * CO + col];
        else if (col == 64) v = 1.0f;
    }
    __nv_bfloat16 h = __float2bfloat16(v);
    g_Vthi[idx] = h;
    g_Vtlo[idx] = __float2bfloat16(v - __bfloat162float(h));
}

// ---------------- 6) GEMM1: split-bf16, 128x128, 2-stage k32, dead-tile skip ----------------
#define G1_PLANE 10240              // 128 rows * 80 bytes
#define G1_SMEM  (2 * 4 * G1_PLANE) // 81920

__device__ __forceinline__ void g1_prefetch(uint32_t sb, int buf, int kc,
                                            int pb, int qb, int t) {
    int kof = kc * 32;
#pragma unroll
    for (int i = 0; i < 8; i++) {
        int v = t + i * 256;
        int plane = v >> 9, r = (v >> 2) & 127, seg = v & 3;
        uint32_t sa = sb + (uint32_t)(buf * (4 * G1_PLANE) + plane * G1_PLANE + r * 80 + seg * 16);
        const __nv_bfloat16* src = (plane == 0) ? g_faHi : (plane == 1) ? g_faLo
                                 : (plane == 2) ? g_fbHi : g_fbLo;
        int row;
        if (plane < 2) row = pb + r;
        else { row = __ldg(&g_perm[qb + r]); if (row < 0) row = 0; }
        cp16(sa, (const char*)src + ((size_t)row * CF + kof + seg * 8) * 2);
    }
}

__global__ void __launch_bounds__(256, 2) k_gemm_mma() {
    if (g_tileSkip[blockIdx.x]) return;
    extern __shared__ char smem[];
    uint32_t sb = smem_u32(smem);
    int t = threadIdx.x, w = t >> 5, l = t & 31;
    int qb = blockIdx.x << 7, pb = blockIdx.y << 7;
    int wm = w >> 1, wn = w & 1;

    float acc[2][8][4] = {};

    int rowA = wm * 32 + (l & 15);
    int rowB = wn * 64 + (l & 15);
    uint32_t colb = (uint32_t)((l >> 4) << 4);

    g1_prefetch(sb, 0, 0, pb, qb, t); CP_COMMIT;

    for (int kc = 0; kc < 8; kc++) {
        if (kc < 7) { g1_prefetch(sb, (kc + 1) & 1, kc + 1, pb, qb, t); CP_COMMIT; CP_WAIT1; }
        else CP_WAIT0;
        __syncthreads();

        uint32_t baseA = sb + (uint32_t)((kc & 1) * (4 * G1_PLANE));
        uint32_t baseB = baseA + 2 * G1_PLANE;

#pragma unroll
        for (int kk2 = 0; kk2 < 2; kk2++) {
            uint32_t kb = (uint32_t)(kk2 * 32) + colb;
            uint32_t ah[2][4], al[2][4];
#pragma unroll
            for (int mi = 0; mi < 2; mi++) {
                uint32_t ad = baseA + (uint32_t)((rowA + mi * 16) * 80) + kb;
                LDSM_X4(ah[mi][0], ah[mi][1], ah[mi][2], ah[mi][3], ad);
                LDSM_X4(al[mi][0], al[mi][1], al[mi][2], al[mi][3], ad + G1_PLANE);
            }
#pragma unroll
            for (int np = 0; np < 4; np++) {
                uint32_t bd = baseB + (uint32_t)((rowB + np * 16) * 80) + kb;
                uint32_t bh[4], bl[4];
                LDSM_X4(bh[0], bh[1], bh[2], bh[3], bd);
                LDSM_X4(bl[0], bl[1], bl[2], bl[3], bd + G1_PLANE);
                mma_bf16(acc[0][np * 2 + 0], ah[0], bh[0], bh[2]);
                mma_bf16(acc[0][np * 2 + 1], ah[0], bh[1], bh[3]);
                mma_bf16(acc[1][np * 2 + 0], ah[1], bh[0], bh[2]);
                mma_bf16(acc[1][np * 2 + 1], ah[1], bh[1], bh[3]);
                mma_bf16(acc[0][np * 2 + 0], ah[0], bl[0], bl[2]);
                mma_bf16(acc[0][np * 2 + 1], ah[0], bl[1], bl[3]);
                mma_bf16(acc[1][np * 2 + 0], ah[1], bl[0], bl[2]);
                mma_bf16(acc[1][np * 2 + 1], ah[1], bl[1], bl[3]);
                mma_bf16(acc[0][np * 2 + 0], al[0], bh[0], bh[2]);
                mma_bf16(acc[0][np * 2 + 1], al[0], bh[1], bh[3]);
                mma_bf16(acc[1][np * 2 + 0], al[1], bh[0], bh[2]);
                mma_bf16(acc[1][np * 2 + 1], al[1], bh[1], bh[3]);
            }
        }
        __syncthreads();
    }

    // ---- epilogue: exp + bf16 X store (hi plane only) ----
    int prl = wm * 32 + (l >> 2);
    int qcl = wn * 64 + (l & 3) * 2;
#pragma unroll
    for (int mi = 0; mi < 2; mi++) {
#pragma unroll
        for (int nj = 0; nj < 8; nj++) {
#pragma unroll
            for (int half = 0; half < 2; half++) {
                int rloc = prl + mi * 16 + half * 8;
                int qloc = qcl + nj * 8;
                float x0 = __expf(fminf(ALPHA * acc[mi][nj][half * 2 + 0], 80.f));
                float x1 = __expf(fminf(ALPHA * acc[mi][nj][half * 2 + 1], 80.f));
                __nv_bfloat16 h0 = __float2bfloat16(x0);
                __nv_bfloat16 h1 = __float2bfloat16(x1);
                __nv_bfloat162 hp; hp.x = h0; hp.y = h1;
                size_t idx = ((size_t)(pb + rloc) * XQ + qb + qloc) >> 1;
                g_Xhi[idx] = *(uint32_t*)&hp;
            }
        }
    }
}

// ---------------- 7) GEMM2: 128-row CTAs, hi-only X, 2 combos, dead-chunk skip ----------------
#define W2RS 48
#define W2A (128 * W2RS)                // 6144 (single X plane)
#define W2B (NV2 * W2RS)                // 3840
#define W2ST (W2A + 2 * W2B)            // 13824
#define W2SMEM (4 * W2ST)               // 55296
#define W2SLOTS (256 + 320)             // A: 128x2, B: 80x2x2

__device__ __forceinline__ void g2_prefetch(uint32_t sb, int s, int qof, int pb, int t) {
#pragma unroll
    for (int i = 0; i < 3; i++) {
        int v = t + i * 256;
        if (v >= W2SLOTS) break;
        if (v < 256) {
            int r = v >> 1, seg = v & 1;
            uint32_t sa = sb + (uint32_t)(s * W2ST + r * W2RS + seg * 16);
            cp16(sa, (const char*)g_Xhi + ((size_t)(pb + r) * XQ + qof) * 2 + seg * 16);
        } else {
            int v2 = v - 256;
            int plane = (v2 >= NV2 * 2) ? 1 : 0;
            int r = (v2 - plane * NV2 * 2) >> 1, seg = v2 & 1;
            uint32_t sa = sb + (uint32_t)(s * W2ST + W2A + plane * W2B + r * W2RS + seg * 16);
            const __nv_bfloat16* vp = plane ? g_Vtlo : g_Vthi;
            cp16(sa, (const char*)vp + ((size_t)r * XQ + qof + seg * 8) * 2);
        }
    }
}

__device__ __forceinline__ void g2_flush(float acc[2][6][4], int nt, int pb, int wm, int wn,
                                         int l, int plane, int slot, int seg) {
    float* Wp = g_Wpart + (size_t)(plane * 4 + slot) * HW * NV2;
    int cb2 = (l & 3) * 2;
#pragma unroll
    for (int mi = 0; mi < 2; mi++) {
        int r0 = pb + wm * 32 + mi * 16 + (threadIdx.x % 32 >> 2);
#pragma unroll
        for (int np = 0; np < 3; np++) {
            if (np < nt) {
#pragma unroll
                for (int n8 = 0; n8 < 2; n8++) {
                    int col = wn * 48 + np * 16 + n8 * 8 + cb2;
                    float* a = acc[mi][np * 2 + n8];
                    *(float2*)&Wp[(size_t)r0 * NV2 + col]       = make_float2(a[0], a[1]);
                    *(float2*)&Wp[(size_t)(r0 + 8) * NV2 + col] = make_float2(a[2], a[3]);
                    a[0] = a[1] = a[2] = a[3] = 0.f;
                }
            }
        }
    }
    if (threadIdx.x == 0) g_slotSeg[plane * 4 + slot] = (unsigned char)seg;
    (void)l;
}

__global__ void __launch_bounds__(256, 2) k_gemm2() {
    extern __shared__ char smem[];
    uint32_t sb = smem_u32(smem);
    int t = threadIdx.x, w = t >> 5, l = t & 31;
    int pb = blockIdx.x << 7;         // 128 rows per CTA, grid.x = 32
    int plane = blockIdx.y;           // 0..7
    int cbase = plane * 33;
    int q0 = plane * 528;
    int wm = w & 3, wn = w >> 2;
    int nt = wn ? 2 : 3;

    float acc[2][6][4] = {};
    int curSeg = g_chunkSeg[cbase];
    int slot = 0;

    uint32_t colb = (uint32_t)((l >> 4) << 4);

    g2_prefetch(sb, 0, q0, pb, t); CP_COMMIT;
    g2_prefetch(sb, 1, q0 + 16, pb, t); CP_COMMIT;
    g2_prefetch(sb, 2, q0 + 32, pb, t); CP_COMMIT;

    for (int kc = 0; kc < 33; kc++) {
        CP_WAIT2;
        __syncthreads();
        if (kc <= 29) g2_prefetch(sb, (kc + 3) & 3, q0 + (kc + 3) * 16, pb, t);
        CP_COMMIT;

        int sg = g_chunkSeg[cbase + kc];
        if (sg != curSeg) {
            if (curSeg) {
                g2_flush(acc, nt, pb, wm, wn, l, plane, slot, curSeg);
                slot = min(slot + 1, 3);
            }
            curSeg = sg;
        }
        if (!sg) continue;            // dead chunk (code 0 / pad)

        uint32_t baseA = sb + (uint32_t)((kc & 3) * W2ST);
        uint32_t baseB = baseA + W2A;

        uint32_t ah[2][4];
#pragma unroll
        for (int mi = 0; mi < 2; mi++) {
            uint32_t ad = baseA + (uint32_t)((wm * 32 + mi * 16 + (l & 15)) * W2RS) + colb;
            LDSM_X4(ah[mi][0], ah[mi][1], ah[mi][2], ah[mi][3], ad);
        }
#pragma unroll
        for (int np = 0; np < 3; np++) {
            if (np < nt) {
                uint32_t bd = baseB + (uint32_t)((wn * 48 + np * 16 + (l & 15)) * W2RS) + colb;
                uint32_t bh[4], bl[4];
                LDSM_X4(bh[0], bh[1], bh[2], bh[3], bd);
                LDSM_X4(bl[0], bl[1], bl[2], bl[3], bd + W2B);
                mma_bf16(acc[0][np * 2 + 0], ah[0], bh[0], bh[2]);
                mma_bf16(acc[0][np * 2 + 1], ah[0], bh[1], bh[3]);
                mma_bf16(acc[1][np * 2 + 0], ah[1], bh[0], bh[2]);
                mma_bf16(acc[1][np * 2 + 1], ah[1], bh[1], bh[3]);
                mma_bf16(acc[0][np * 2 + 0], ah[0], bl[0], bl[2]);
                mma_bf16(acc[0][np * 2 + 1], ah[0], bl[1], bl[3]);
                mma_bf16(acc[1][np * 2 + 0], ah[1], bl[0], bl[2]);
                mma_bf16(acc[1][np * 2 + 1], ah[1], bl[1], bl[3]);
            }
        }
    }
    if (curSeg) g2_flush(acc, nt, pb, wm, wn, l, plane, slot, curSeg);
}

// ---------------- 8) combine: sum slots by code-bit membership ----------------
__global__ void k_combine() {
    int idx = blockIdx.x * 256 + threadIdx.x;   // p*64 + c
    if (idx >= HW * CO) return;
    int p = idx >> 6, c = idx & 63;
    float Wk[3] = {0.f, 0.f, 0.f}, Ek[3] = {0.f, 0.f, 0.f};
#pragma unroll
    for (int s = 0; s < 32; s++) {
        int sg = g_slotSeg[s];
        if (!sg) continue;
        const float* Wp = g_Wpart + (size_t)s * HW * NV2 + (size_t)p * NV2;
        float wv = Wp[c], ev = Wp[64];
        if (sg & 1) { Wk[0] += wv; Ek[0] += ev; }
        if (sg & 2) { Wk[1] += wv; Ek[1] += ev; }
        if (sg & 4) { Wk[2] += wv; Ek[2] += ev; }
    }
    float comb = 0.f, msum = 0.f;
#pragma unroll
    for (int k = 0; k < 3; k++) {
        if (g_maskA[k * HW + p]) {
            msum += 1.f;
            float denom = Ek[k] + (4096.0f - g_nbk[k]);
            comb += (Wk[k] + g_U0[c] - g_Bk[k * CO + c]) / denom;
        }
    }
    g_aligned[idx] = comb / fmaxf(msum, 1.0f);
}

// ---------------- 9) bilinear upsample 64 -> 256 ----------------
__global__ void __launch_bounds__(256) k_up(float* __restrict__ out) {
    __shared__ float sm[64 * 65];
    int t = threadIdx.x;
    int Y = blockIdx.x;
    const float sc = 63.0f / 255.0f;
    float ry = (float)Y * sc;
    int y0 = (int)ry;
    int y1 = min(y0 + 1, 63);
    float wy = ry - (float)y0;

    const float* A0 = g_aligned + (size_t)(y0 << 6) * CO;
    const float* A1 = g_aligned + (size_t)(y1 << 6) * CO;
#pragma unroll
    for (int i = 0; i < 16; i++) {
        int v = t + i * 256;
        int x = v >> 6, c = v & 63;
        float a = A0[v], b = A1[v];
        sm[c * 65 + x] = a + (b - a) * wy;
    }
    __syncthreads();

#pragma unroll
    for (int i = 0; i < 64; i++) {
        int v = t + i * 256;
        int c = v >> 8, X = v & 255;
        float rx = (float)X * sc;
        int x0 = (int)rx;
        int x1 = min(x0 + 1, 63);
        float wx = rx - (float)x0;
        float a = sm[c * 65 + x0], b = sm[c * 65 + x1];
        out[(size_t)c * 65536 + Y * 256 + X] = a + (b - a) * wx;
    }
}

// ---------------- launch ----------------
extern "C" void kernel_launch(void* const* d_in, const int* in_sizes, int n_in,
                              void* d_out, int out_size) {
    const float* ufb_in = (const float*)d_in[0];   // (1,64,256,256)
    const float* fa     = (const float*)d_in[1];   // (1,256,64,64)
    const int*   fap    = (const int*)  d_in[2];   // (1,4,256,256)
    const float* fb     = (const float*)d_in[3];   // (1,256,64,64)
    const int*   fbp    = (const int*)  d_in[4];   // (1,4,256,256)
    float* out = (float*)d_out;                    // (1,64,256,256)

    static cudaStream_t s1 = nullptr;
    static cudaEvent_t e0 = nullptr, ePerm = nullptr, eV = nullptr;
    if (!s1) {
        cudaStreamCreateWithFlags(&s1, cudaStreamNonBlocking);
        cudaEventCreateWithFlags(&e0, cudaEventDisableTiming);
        cudaEventCreateWithFlags(&ePerm, cudaEventDisableTiming);
        cudaEventCreateWithFlags(&eV, cudaEventDisableTiming);
        cudaFuncSetAttribute(k_gemm_mma, cudaFuncAttributeMaxDynamicSharedMemorySize, G1_SMEM);
        cudaFuncSetAttribute(k_gemm2,    cudaFuncAttributeMaxDynamicSharedMemorySize, W2SMEM);
    }

    // fork
    cudaEventRecord(e0, 0);
    cudaStreamWaitEvent(s1, e0, 0);

    k_maskperm<<<1, 512, 0, s1>>>(fap, fbp);               // 1 (s1): masks + sort
    cudaEventRecord(ePerm, s1);
    k_mean<<<512, 256>>>(fa, fb);                          // 2 (s0)
    k_norm<<<dim3(128, 2), 256>>>(fa, fb);                 // 3 (s0)
    cudaStreamWaitEvent(0, ePerm, 0);
    k_gemm_mma<<<dim3(NQT, 32), 256, G1_SMEM>>>();         // 4 (s0) -> profiled
    k_ufb<<<(HW * CO) / 256, 256, 0, s1>>>(ufb_in);        // 5 (s1, overlaps GEMM1)
    k_ub<<<64, 256, 0, s1>>>();                            // 6 (s1)
    k_V<<<(NV2 * XQ + 255) / 256, 256, 0, s1>>>();         // 7 (s1)
    cudaEventRecord(eV, s1);
    cudaStreamWaitEvent(0, eV, 0);

    k_gemm2<<<dim3(32, 8), 256, W2SMEM>>>();
    k_combine<<<(HW * CO) / 256, 256>>>();
    k_up<<<256, 256>>>(out);
}